// round 2
// baseline (speedup 1.0000x reference)
#include <cuda_runtime.h>
#include <cuda_bf16.h>

#define TM 64          // nodes per block
#define HS 130         // smem row stride (floats), pad so 8*HS % 32 != 0
#define NEG_INF -1e10f

__global__ __launch_bounds__(128, 4)
void agg_kernel(const float* __restrict__ self_vecs,   // [N,128]
                const float* __restrict__ neigh,       // [N,32,128]
                const int*   __restrict__ mask,        // [N,32]
                const float* __restrict__ W,           // [128,128]
                float*       __restrict__ out,         // [N,256]
                int N)
{
    __shared__ float H[TM * HS];

    const int tid  = threadIdx.x;
    const int lane = tid & 31;
    const int warp = tid >> 5;          // 0..3
    const int n0   = blockIdx.x * TM;

    // ---------------- Phase 1: masked max-pool + self relu copy ----------------
    // warp w handles local nodes w*16 .. w*16+15
    #pragma unroll 1
    for (int i = 0; i < TM / 4 / 4; ) { i = i; break; }  // (no-op; keep compiler calm)

    for (int i = 0; i < 16; i++) {
        const int ln = warp * 16 + i;
        const int n  = n0 + ln;
        float* hrow = H + ln * HS + lane * 4;
        if (n < N) {
            // one mask element per lane -> ballot = 32-bit validity mask
            const int mv = mask[n * 32 + lane];
            const unsigned vm = __ballot_sync(0xffffffffu, mv > 0);

            float4 m = make_float4(NEG_INF, NEG_INF, NEG_INF, NEG_INF);
            const float4* np = reinterpret_cast<const float4*>(neigh + (size_t)n * 32 * 128) + lane;
            #pragma unroll 4
            for (int k = 0; k < 32; k++) {
                if ((vm >> k) & 1u) {
                    float4 v = np[(size_t)k * 32];
                    m.x = fmaxf(m.x, v.x);
                    m.y = fmaxf(m.y, v.y);
                    m.z = fmaxf(m.z, v.z);
                    m.w = fmaxf(m.w, v.w);
                }
            }
            // scalar stores (row stride 130 floats is not 16B-aligned per row)
            hrow[0] = m.x; hrow[1] = m.y; hrow[2] = m.z; hrow[3] = m.w;

            // fused self path: relu(self) -> out[:, 0:128]
            float4 s = reinterpret_cast<const float4*>(self_vecs + (size_t)n * 128)[lane];
            s.x = fmaxf(s.x, 0.f); s.y = fmaxf(s.y, 0.f);
            s.z = fmaxf(s.z, 0.f); s.w = fmaxf(s.w, 0.f);
            reinterpret_cast<float4*>(out + (size_t)n * 256)[lane] = s;
        } else {
            hrow[0] = 0.f; hrow[1] = 0.f; hrow[2] = 0.f; hrow[3] = 0.f;
        }
    }
    __syncthreads();

    // ---------------- Phase 2: C[64x128] = H[64x128] @ W[128x128] ----------------
    // 128 threads as 8(ty) x 16(tx); each thread owns an 8x8 micro-tile.
    const int tx = tid & 15;      // 0..15 -> 8 output cols each
    const int ty = tid >> 4;      // 0..7  -> 8 node rows each

    float acc[8][8];
    #pragma unroll
    for (int i = 0; i < 8; i++)
        #pragma unroll
        for (int j = 0; j < 8; j++)
            acc[i][j] = 0.f;

    const float* wbase = W + tx * 8;

    #pragma unroll 4
    for (int kk = 0; kk < 128; kk++) {
        float a[8];
        #pragma unroll
        for (int i = 0; i < 8; i++)
            a[i] = H[(ty * 8 + i) * HS + kk];

        const float4 b0 = __ldg(reinterpret_cast<const float4*>(wbase + kk * 128));
        const float4 b1 = __ldg(reinterpret_cast<const float4*>(wbase + kk * 128 + 4));

        #pragma unroll
        for (int i = 0; i < 8; i++) {
            acc[i][0] = fmaf(a[i], b0.x, acc[i][0]);
            acc[i][1] = fmaf(a[i], b0.y, acc[i][1]);
            acc[i][2] = fmaf(a[i], b0.z, acc[i][2]);
            acc[i][3] = fmaf(a[i], b0.w, acc[i][3]);
            acc[i][4] = fmaf(a[i], b1.x, acc[i][4]);
            acc[i][5] = fmaf(a[i], b1.y, acc[i][5]);
            acc[i][6] = fmaf(a[i], b1.z, acc[i][6]);
            acc[i][7] = fmaf(a[i], b1.w, acc[i][7]);
        }
    }

    // relu + store to out[:, 128:256]
    #pragma unroll
    for (int i = 0; i < 8; i++) {
        const int n = n0 + ty * 8 + i;
        if (n < N) {
            float4 c0, c1;
            c0.x = fmaxf(acc[i][0], 0.f); c0.y = fmaxf(acc[i][1], 0.f);
            c0.z = fmaxf(acc[i][2], 0.f); c0.w = fmaxf(acc[i][3], 0.f);
            c1.x = fmaxf(acc[i][4], 0.f); c1.y = fmaxf(acc[i][5], 0.f);
            c1.z = fmaxf(acc[i][6], 0.f); c1.w = fmaxf(acc[i][7], 0.f);
            float* op = out + (size_t)n * 256 + 128 + tx * 8;
            reinterpret_cast<float4*>(op)[0] = c0;
            reinterpret_cast<float4*>(op)[1] = c1;
        }
    }
}

extern "C" void kernel_launch(void* const* d_in, const int* in_sizes, int n_in,
                              void* d_out, int out_size)
{
    const float* self_vecs = (const float*)d_in[0];   // [N,128]
    const float* neigh     = (const float*)d_in[1];   // [N,32,128]
    const int*   mask      = (const int*)  d_in[2];   // [N,32]
    const float* W         = (const float*)d_in[3];   // [128,128]
    float* out = (float*)d_out;                        // [N,256]

    const int N = in_sizes[0] / 128;
    const int grid = (N + TM - 1) / TM;
    agg_kernel<<<grid, 128>>>(self_vecs, neigh, mask, W, out, N);
}

// round 3
// speedup vs baseline: 1.5078x; 1.5078x over previous
#include <cuda_runtime.h>
#include <cuda_bf16.h>

#define NEG_INF -1e10f
#define MAX_N 50176

// scratch for pooled neighbor features [N,128]
__device__ float g_H[MAX_N * 128];

// ---------------------------------------------------------------------------
// Kernel 1: masked neighbor max-pool (one warp per node) + fused self-relu
// ---------------------------------------------------------------------------
__global__ __launch_bounds__(256)
void pool_kernel(const float* __restrict__ self_vecs,   // [N,128]
                 const float* __restrict__ neigh,       // [N,32,128]
                 const int*   __restrict__ mask,        // [N,32]
                 float*       __restrict__ out,         // [N,256]
                 int N)
{
    const int gwarp = (blockIdx.x * blockDim.x + threadIdx.x) >> 5;
    const int lane  = threadIdx.x & 31;
    if (gwarp >= N) return;
    const int n = gwarp;

    // one mask element per lane -> ballot = 32-bit validity mask
    const int mv = mask[n * 32 + lane];
    const unsigned vm = __ballot_sync(0xffffffffu, mv > 0);

    float4 m = make_float4(NEG_INF, NEG_INF, NEG_INF, NEG_INF);
    const float4* np = reinterpret_cast<const float4*>(neigh + (size_t)n * 32 * 128) + lane;

    // fully unrolled, predicated loads: independent -> high MLP,
    // predicate-false rows issue no DRAM traffic.
    #pragma unroll
    for (int k = 0; k < 32; k++) {
        if ((vm >> k) & 1u) {
            float4 v = np[(size_t)k * 32];
            m.x = fmaxf(m.x, v.x);
            m.y = fmaxf(m.y, v.y);
            m.z = fmaxf(m.z, v.z);
            m.w = fmaxf(m.w, v.w);
        }
    }

    reinterpret_cast<float4*>(g_H + (size_t)n * 128)[lane] = m;

    // fused self path: relu(self) -> out[:, 0:128]
    float4 s = reinterpret_cast<const float4*>(self_vecs + (size_t)n * 128)[lane];
    s.x = fmaxf(s.x, 0.f); s.y = fmaxf(s.y, 0.f);
    s.z = fmaxf(s.z, 0.f); s.w = fmaxf(s.w, 0.f);
    reinterpret_cast<float4*>(out + (size_t)n * 256)[lane] = s;
}

// ---------------------------------------------------------------------------
// Kernel 2: out[:,128:256] = relu(H[N,128] @ W[128,128])
// 64-node tile per block, 128 threads as 8(ty) x 16(tx), 8x8 micro-tile.
// ---------------------------------------------------------------------------
#define TM 64
#define HS 132   // smem row stride (floats); multiple of 4 for float4 stores

__global__ __launch_bounds__(128, 4)
void gemm_kernel(const float* __restrict__ W,    // [128,128]
                 float*       __restrict__ out,  // [N,256]
                 int N)
{
    __shared__ float Hs[TM * HS];

    const int tid = threadIdx.x;
    const int n0  = blockIdx.x * TM;

    // cooperative load of the 64x128 H tile (float4, coalesced)
    {
        const int nrows = min(TM, N - n0);
        #pragma unroll
        for (int it = 0; it < (TM * 32) / 128; it++) {
            const int idx = it * 128 + tid;         // 0 .. 2047
            const int row = idx >> 5;               // 0..63
            const int c4  = idx & 31;               // float4 column
            float4 v = (row < nrows)
                ? reinterpret_cast<const float4*>(g_H + (size_t)(n0 + row) * 128)[c4]
                : make_float4(0.f, 0.f, 0.f, 0.f);
            reinterpret_cast<float4*>(Hs + row * HS)[c4] = v;
        }
    }
    __syncthreads();

    const int tx = tid & 15;      // 0..15 -> 8 output cols each
    const int ty = tid >> 4;      // 0..7  -> 8 node rows each

    float acc[8][8];
    #pragma unroll
    for (int i = 0; i < 8; i++)
        #pragma unroll
        for (int j = 0; j < 8; j++)
            acc[i][j] = 0.f;

    const float* wbase = W + tx * 8;

    #pragma unroll 4
    for (int kk = 0; kk < 128; kk++) {
        float a[8];
        #pragma unroll
        for (int i = 0; i < 8; i++)
            a[i] = Hs[(ty * 8 + i) * HS + kk];

        const float4 b0 = __ldg(reinterpret_cast<const float4*>(wbase + kk * 128));
        const float4 b1 = __ldg(reinterpret_cast<const float4*>(wbase + kk * 128 + 4));

        #pragma unroll
        for (int i = 0; i < 8; i++) {
            acc[i][0] = fmaf(a[i], b0.x, acc[i][0]);
            acc[i][1] = fmaf(a[i], b0.y, acc[i][1]);
            acc[i][2] = fmaf(a[i], b0.z, acc[i][2]);
            acc[i][3] = fmaf(a[i], b0.w, acc[i][3]);
            acc[i][4] = fmaf(a[i], b1.x, acc[i][4]);
            acc[i][5] = fmaf(a[i], b1.y, acc[i][5]);
            acc[i][6] = fmaf(a[i], b1.z, acc[i][6]);
            acc[i][7] = fmaf(a[i], b1.w, acc[i][7]);
        }
    }

    #pragma unroll
    for (int i = 0; i < 8; i++) {
        const int n = n0 + ty * 8 + i;
        if (n < N) {
            float4 c0, c1;
            c0.x = fmaxf(acc[i][0], 0.f); c0.y = fmaxf(acc[i][1], 0.f);
            c0.z = fmaxf(acc[i][2], 0.f); c0.w = fmaxf(acc[i][3], 0.f);
            c1.x = fmaxf(acc[i][4], 0.f); c1.y = fmaxf(acc[i][5], 0.f);
            c1.z = fmaxf(acc[i][6], 0.f); c1.w = fmaxf(acc[i][7], 0.f);
            float* op = out + (size_t)n * 256 + 128 + tx * 8;
            reinterpret_cast<float4*>(op)[0] = c0;
            reinterpret_cast<float4*>(op)[1] = c1;
        }
    }
}

extern "C" void kernel_launch(void* const* d_in, const int* in_sizes, int n_in,
                              void* d_out, int out_size)
{
    const float* self_vecs = (const float*)d_in[0];   // [N,128]
    const float* neigh     = (const float*)d_in[1];   // [N,32,128]
    const int*   mask      = (const int*)  d_in[2];   // [N,32]
    const float* W         = (const float*)d_in[3];   // [128,128]
    float* out = (float*)d_out;                        // [N,256]

    const int N = in_sizes[0] / 128;

    // kernel 1: one warp per node
    const int warps_per_block = 8;                     // 256 threads
    const int grid1 = (N + warps_per_block - 1) / warps_per_block;
    pool_kernel<<<grid1, 256>>>(self_vecs, neigh, mask, out, N);

    // kernel 2: 64-node tiles
    const int grid2 = (N + TM - 1) / TM;
    gemm_kernel<<<grid2, 128>>>(W, out, N);
}